// round 9
// baseline (speedup 1.0000x reference)
#include <cuda_runtime.h>
#include <cstdint>

#define BQ     32
#define NKEYS  4096
#define DIM    64
#define NQ     8
#define CPB    32         // chunks per batch -> grid 1024
#define CHUNK  128        // keys per CTA (4 warps x 32)
#define WKEYS  32
#define TKEYS  4          // keys per warp-tile
#define NT     8          // tiles per warp
#define NBUF   2
#define KROW   80         // padded row stride (floats): 16-float chunks at 0,20,40,60

typedef unsigned long long u64;

// ---- global scratch ----
__device__ float    g_pv[BQ * CPB * NQ * DIM];
__device__ float    g_cs[BQ * CPB * NQ];
__device__ unsigned g_cnt[BQ];

// ---- cp.async ----
__device__ __forceinline__ void cp16(uint32_t s, const float* g) {
    asm volatile("cp.async.cg.shared.global [%0], [%1], 16;\n" :: "r"(s), "l"(g));
}
__device__ __forceinline__ void cp_commit() {
    asm volatile("cp.async.commit_group;\n" ::: "memory");
}
template <int N>
__device__ __forceinline__ void cp_wait() {
    asm volatile("cp.async.wait_group %0;\n" :: "n"(N) : "memory");
}

// ---- packed f32x2 ----
__device__ __forceinline__ void fma2(u64& d, u64 a, u64 b) {
    asm("fma.rn.f32x2 %0, %1, %2, %0;" : "+l"(d) : "l"(a), "l"(b));
}
__device__ __forceinline__ float f2lo(u64 x) { return __uint_as_float((unsigned)x); }
__device__ __forceinline__ float f2hi(u64 x) { return __uint_as_float((unsigned)(x >> 32)); }
__device__ __forceinline__ u64 splat2(float p) {
    u64 r; asm("mov.b64 %0, {%1, %1};" : "=l"(r) : "f"(p)); return r;
}
__device__ __forceinline__ u64 pack2(float lo, float hi) {
    u64 r; asm("mov.b64 %0, {%1, %2};" : "=l"(r) : "f"(lo), "f"(hi)); return r;
}

// ---- smem layout (floats) ----
// per warp: NBUF bufs of [K tile (4x80) | V tile (4x80)] = 640 floats each
#define BUF_SZ  (2 * TKEYS * KROW)             // 640
#define W_SZ    (NBUF * BUF_SZ)                // 1280
#define OFF_W(w) ((w) * W_SZ)
#define SMEM_FLOATS (4 * W_SZ)                 // 5120 floats = 20,480 B
// epilogue overlay per warp: pv red [8m][64v] = 512 floats, cs[8] at +512

extern __shared__ float smem[];

__global__ __launch_bounds__(128, 7)
void attn_fused(const float* __restrict__ keys,
                const float* __restrict__ vals,
                const float* __restrict__ query,
                float* __restrict__ out) {
    const int tid  = threadIdx.x;
    const int lane = tid & 31;
    const int warp = tid >> 5;
    const int m    = lane & 7;            // query owned by this lane
    const int kg   = lane >> 3;           // 16-dim chunk group
    const int b     = blockIdx.x >> 5;
    const int chunk = blockIdx.x & 31;
    const int n0    = chunk * CHUNK;
    __shared__ int s_last;

    const uint32_t sbase = (uint32_t)__cvta_generic_to_shared(smem);
    const uint32_t wbase = sbase + (uint32_t)(OFF_W(warp) << 2);

    const float* kgp = keys + ((size_t)b * NKEYS + n0 + warp * WKEYS) * DIM;
    const float* vgp = vals + ((size_t)b * NKEYS + n0 + warp * WKEYS) * DIM;

    // ---- stage tile t into ring slot t%NBUF: 4 keys K + V, padded chunks ----
    auto stage = [&](int t) {
        const int buf = t % NBUF;
        const float* kt = kgp + t * TKEYS * DIM;
        const float* vt = vgp + t * TKEYS * DIM;
        const uint32_t kd = wbase + (uint32_t)((buf * BUF_SZ) << 2);
        const uint32_t vd = kd + (uint32_t)((TKEYS * KROW) << 2);
#pragma unroll
        for (int i = 0; i < 2; ++i) {              // K: 64 x 16B
            int c = i * 32 + lane;
            int key = c >> 4, ch = c & 15;
            int cg = ch >> 2, j = ch & 3;
            cp16(kd + (uint32_t)((key * KROW + cg * 20 + j * 4) << 2),
                 kt + key * DIM + cg * 16 + j * 4);
        }
#pragma unroll
        for (int i = 0; i < 2; ++i) {              // V: 64 x 16B
            int c = i * 32 + lane;
            int key = c >> 4, ch = c & 15;
            int cg = ch >> 2, j = ch & 3;
            cp16(vd + (uint32_t)((key * KROW + cg * 20 + j * 4) << 2),
                 vt + key * DIM + cg * 16 + j * 4);
        }
        cp_commit();
    };

    stage(0); stage(1);

    // ---- Q[m][16kg..+15] into registers, prescaled by 1/8 ----
    u64 q[8];
    {
        const float* qp = query + ((size_t)b * NQ + m) * DIM + kg * 16;
#pragma unroll
        for (int j = 0; j < 8; ++j)
            q[j] = pack2(qp[2 * j] * 0.125f, qp[2 * j + 1] * 0.125f);
    }

    float cs = 0.f;
    u64 pv[8];
#pragma unroll
    for (int i = 0; i < 8; ++i) pv[i] = 0ull;

    for (int t = 0; t < NT; ++t) {
        if (t < NT - 1) cp_wait<1>(); else cp_wait<0>();
        __syncwarp();

        const float* Kb = &smem[OFF_W(warp) + (t % NBUF) * BUF_SZ];
        const float* Vb = Kb + TKEYS * KROW;

#pragma unroll
        for (int k = 0; k < TKEYS; ++k) {
            // ---- QK: 16-dim partial dot (1 wf per LDS.128 via pad-20 chunks) ----
            const float* kr = Kb + k * KROW + kg * 20;
            ulonglong2 k01 = *(const ulonglong2*)(kr);
            ulonglong2 k23 = *(const ulonglong2*)(kr + 4);
            ulonglong2 k45 = *(const ulonglong2*)(kr + 8);
            ulonglong2 k67 = *(const ulonglong2*)(kr + 12);
            u64 acc = 0ull;
            fma2(acc, k01.x, q[0]); fma2(acc, k01.y, q[1]);
            fma2(acc, k23.x, q[2]); fma2(acc, k23.y, q[3]);
            fma2(acc, k45.x, q[4]); fma2(acc, k45.y, q[5]);
            fma2(acc, k67.x, q[6]); fma2(acc, k67.y, q[7]);
            float a = f2lo(acc) + f2hi(acc);
            // butterfly over the 4 kg groups -> every lane holds full dot
            a += __shfl_xor_sync(0xffffffffu, a, 8);
            a += __shfl_xor_sync(0xffffffffu, a, 16);
            // softmax over the 8 m lanes — no max shift (|a| <~ 6, exp safe)
            float e = __expf(a);
            float sum = e;
            sum += __shfl_xor_sync(0xffffffffu, sum, 1);
            sum += __shfl_xor_sync(0xffffffffu, sum, 2);
            sum += __shfl_xor_sync(0xffffffffu, sum, 4);
            float p = __fdividef(e, sum) + 1e-8f;
            cs += p;
            // ---- PV: lane accumulates out[m][16kg..+15] ----
            u64 pp = splat2(p);
            const float* vr = Vb + k * KROW + kg * 20;
            ulonglong2 v01 = *(const ulonglong2*)(vr);
            ulonglong2 v23 = *(const ulonglong2*)(vr + 4);
            ulonglong2 v45 = *(const ulonglong2*)(vr + 8);
            ulonglong2 v67 = *(const ulonglong2*)(vr + 12);
            fma2(pv[0], pp, v01.x); fma2(pv[1], pp, v01.y);
            fma2(pv[2], pp, v23.x); fma2(pv[3], pp, v23.y);
            fma2(pv[4], pp, v45.x); fma2(pv[5], pp, v45.y);
            fma2(pv[6], pp, v67.x); fma2(pv[7], pp, v67.y);
        }
        __syncwarp();
        if (t + 2 < NT) stage(t + 2);
    }

    // ---- epilogue: lane's 16 floats are a unique (m, kg) slice -> no reduce ----
    {
        float* red = &smem[OFF_W(warp)];     // ring fully drained
        u64* dst = (u64*)&red[m * 64 + kg * 16];
#pragma unroll
        for (int j = 0; j < 8; ++j) dst[j] = pv[j];
        if (kg == 0) red[512 + m] = cs;      // all kg copies identical
    }
    __syncthreads();

    const int pidx = (b * CPB + chunk) * NQ;
    if (tid < 8) {
        float s = 0.f;
#pragma unroll
        for (int w = 0; w < 4; ++w) s += smem[OFF_W(w) + 512 + tid];
        g_cs[pidx + tid] = s;
    }
    {
        int off = tid * 4;                    // 128 threads x float4 = 512 floats
        float4 s = make_float4(0.f, 0.f, 0.f, 0.f);
#pragma unroll
        for (int w = 0; w < 4; ++w) {
            float4 p = *(const float4*)&smem[OFF_W(w) + off];
            s.x += p.x; s.y += p.y; s.z += p.z; s.w += p.w;
        }
        *(float4*)&g_pv[(size_t)pidx * DIM + off] = s;
    }

    // ---- fused finalize: last chunk CTA of this batch ----
    __syncthreads();
    if (tid == 0) {
        __threadfence();
        unsigned old = atomicAdd(&g_cnt[b], 1u);
        s_last = (old == CPB - 1) ? 1 : 0;
    }
    __syncthreads();
    if (s_last) {
        __threadfence();
        int qm = tid >> 4, v4 = (tid & 15) << 2;
        float c0 = 0.f;
        float4 acc = make_float4(0.f, 0.f, 0.f, 0.f);
#pragma unroll
        for (int c = 0; c < CPB; ++c) {
            c0 += g_cs[(b * CPB + c) * NQ + qm];
            float4 p = *(const float4*)&g_pv[((size_t)(b * CPB + c) * NQ + qm) * DIM + v4];
            acc.x += p.x; acc.y += p.y; acc.z += p.z; acc.w += p.w;
        }
        float inv = 1.0f / c0;
        *(float4*)&out[((size_t)b * NQ + qm) * DIM + v4] =
            make_float4(acc.x * inv, acc.y * inv, acc.z * inv, acc.w * inv);
        if (tid == 0) g_cnt[b] = 0;   // reset for next graph replay
    }
}

extern "C" void kernel_launch(void* const* d_in, const int* in_sizes, int n_in,
                              void* d_out, int out_size) {
    const float* keys  = (const float*)d_in[0];
    const float* vals  = (const float*)d_in[1];
    const float* query = (const float*)d_in[2];
    float* out = (float*)d_out;

    cudaFuncSetAttribute(attn_fused,
                         cudaFuncAttributeMaxDynamicSharedMemorySize,
                         SMEM_FLOATS * sizeof(float));
    attn_fused<<<BQ * CPB, 128, SMEM_FLOATS * sizeof(float)>>>(keys, vals, query, out);
}

// round 10
// speedup vs baseline: 1.2696x; 1.2696x over previous
#include <cuda_runtime.h>
#include <cstdint>

#define BQ     32
#define NKEYS  4096
#define DIM    64
#define NQ     8
#define CPB    32         // chunks per batch -> grid 1024
#define CHUNK  128        // keys per CTA (4 warps x 32)
#define WKEYS  32         // keys per warp; lane = key
#define KHROW  36         // floats per K half-row (32 + 4 pad) -> conflict-free
#define PROW   20         // floats per splatted-P row (16 + 4 pad)

typedef unsigned long long u64;

// ---- global scratch ----
__device__ float    g_pv[BQ * CPB * NQ * DIM];
__device__ float    g_cs[BQ * CPB * NQ];
__device__ unsigned g_cnt[BQ];

// ---- cp.async ----
__device__ __forceinline__ void cp16(uint32_t s, const float* g) {
    asm volatile("cp.async.cg.shared.global [%0], [%1], 16;\n" :: "r"(s), "l"(g));
}
__device__ __forceinline__ void cp_commit() {
    asm volatile("cp.async.commit_group;\n" ::: "memory");
}
template <int N>
__device__ __forceinline__ void cp_wait() {
    asm volatile("cp.async.wait_group %0;\n" :: "n"(N) : "memory");
}

// ---- packed f32x2 ----
__device__ __forceinline__ void fma2(u64& d, u64 a, u64 b) {
    asm("fma.rn.f32x2 %0, %1, %2, %0;" : "+l"(d) : "l"(a), "l"(b));
}
__device__ __forceinline__ float f2lo(u64 x) { return __uint_as_float((unsigned)x); }
__device__ __forceinline__ float f2hi(u64 x) { return __uint_as_float((unsigned)(x >> 32)); }
__device__ __forceinline__ u64 splat2(float p) {
    u64 r; asm("mov.b64 %0, {%1, %1};" : "=l"(r) : "f"(p)); return r;
}

// ---- smem layout (float offsets) ----
// Q (prescaled): 8 x 64 = 512 floats at 0 (uniform reads -> no pad needed)
// per-warp region: KH0 (32x36=1152) | KH1 (1152) | P (32x20=640)
//   KH0/KH1 are reused as V buffers (keys 0-15 / 16-31, VROW=64) during PV,
//   then KH0 is reused as the epilogue reduction area.
#define W_KH0   0
#define W_KH1   1152
#define W_P     2304
#define W_SZ    2944
#define OFF_Q   0
#define OFF_W(w) (512 + (w) * W_SZ)
#define SMEM_FLOATS (512 + 4 * W_SZ)           // 12288 floats = 49,152 B -> 4 CTAs/SM

extern __shared__ float smem[];

__global__ __launch_bounds__(128, 4)
void attn_fused(const float* __restrict__ keys,
                const float* __restrict__ vals,
                const float* __restrict__ query,
                float* __restrict__ out) {
    const int tid  = threadIdx.x;
    const int lane = tid & 31;     // = this lane's key within the warp tile
    const int warp = tid >> 5;
    const int b     = blockIdx.x >> 5;
    const int chunk = blockIdx.x & 31;
    const int n0    = chunk * CHUNK;
    __shared__ int s_last;

    const uint32_t sbase = (uint32_t)__cvta_generic_to_shared(smem);
    const uint32_t wbase = sbase + (uint32_t)(OFF_W(warp) << 2);

    const float* kgp = keys + ((size_t)b * NKEYS + n0 + warp * WKEYS) * DIM;
    const float* vgp = vals + ((size_t)b * NKEYS + n0 + warp * WKEYS) * DIM;

    // ---- stage K half h (dims 32h..32h+31 of all 32 keys) ----
    auto stage_k = [&](int h) {
        const uint32_t kd = wbase + (uint32_t)((h ? W_KH1 : W_KH0) << 2);
#pragma unroll
        for (int i = 0; i < 8; ++i) {
            int c = i * 32 + lane;               // 0..255
            int k = c >> 3, i2 = c & 7;
            cp16(kd + (uint32_t)((k * KHROW + i2 * 4) << 2),
                 kgp + k * DIM + h * 32 + i2 * 4);
        }
        cp_commit();
    };
    // ---- stage V half h (keys 16h..16h+15, full rows) into KH buffer h ----
    auto stage_v = [&](int h) {
        const uint32_t vd = wbase + (uint32_t)((h ? W_KH1 : W_KH0) << 2);
        const float* vt = vgp + h * 16 * DIM;
#pragma unroll
        for (int i = 0; i < 8; ++i) {
            int c = i * 32 + lane;               // 0..255
            int k = c >> 4, i2 = c & 15;
            cp16(vd + (uint32_t)((k * DIM + i2 * 4) << 2),
                 vt + k * DIM + i2 * 4);
        }
        cp_commit();
    };

    stage_k(0);
    stage_k(1);

    // ---- Q into smem, prescaled by 1/8 (uniform-read layout, unpadded) ----
    if (tid < 128) {
        int r = tid >> 4, s = (tid & 15) << 2;
        float4 qv = *(const float4*)(query + ((size_t)b * NQ + r) * DIM + s);
        qv.x *= 0.125f; qv.y *= 0.125f; qv.z *= 0.125f; qv.w *= 0.125f;
        *(float4*)&smem[OFF_Q + r * DIM + s] = qv;
    }
    __syncthreads();

    // ================= QK: lane = key, K distinct, Q uniform =================
    u64 acc[8];
#pragma unroll
    for (int m = 0; m < 8; ++m) acc[m] = 0ull;

    const float* Kr0 = &smem[OFF_W(warp) + W_KH0 + lane * KHROW];
    const float* Kr1 = &smem[OFF_W(warp) + W_KH1 + lane * KHROW];

    cp_wait<1>();  __syncwarp();          // KH0 ready
#pragma unroll
    for (int i = 0; i < 8; ++i) {         // dims 0..31
        ulonglong2 kc = *(const ulonglong2*)(Kr0 + i * 4);
#pragma unroll
        for (int m = 0; m < 8; ++m) {
            ulonglong2 qc = *(const ulonglong2*)&smem[OFF_Q + m * DIM + i * 4];
            fma2(acc[m], kc.x, qc.x);
            fma2(acc[m], kc.y, qc.y);
        }
    }
    stage_v(0);                            // KH0 consumed -> refill with V keys 0-15

    cp_wait<1>();  __syncwarp();          // KH1 ready (Vh0 pending)
#pragma unroll
    for (int i = 0; i < 8; ++i) {         // dims 32..63
        ulonglong2 kc = *(const ulonglong2*)(Kr1 + i * 4);
#pragma unroll
        for (int m = 0; m < 8; ++m) {
            ulonglong2 qc = *(const ulonglong2*)&smem[OFF_Q + m * DIM + 32 + i * 4];
            fma2(acc[m], kc.x, qc.x);
            fma2(acc[m], kc.y, qc.y);
        }
    }
    stage_v(1);                            // KH1 consumed -> refill with V keys 16-31

    // ================= softmax: fully lane-local, no shuffles =================
    {
        float e0 = __expf(f2lo(acc[0]) + f2hi(acc[0]));
        float e1 = __expf(f2lo(acc[1]) + f2hi(acc[1]));
        float e2 = __expf(f2lo(acc[2]) + f2hi(acc[2]));
        float e3 = __expf(f2lo(acc[3]) + f2hi(acc[3]));
        float e4 = __expf(f2lo(acc[4]) + f2hi(acc[4]));
        float e5 = __expf(f2lo(acc[5]) + f2hi(acc[5]));
        float e6 = __expf(f2lo(acc[6]) + f2hi(acc[6]));
        float e7 = __expf(f2lo(acc[7]) + f2hi(acc[7]));
        float sum = ((e0 + e1) + (e2 + e3)) + ((e4 + e5) + (e6 + e7));
        float inv = __fdividef(1.0f, sum);
        float* Pr = &smem[OFF_W(warp) + W_P + lane * PROW];
        u64 pp0 = splat2(fmaf(e0, inv, 1e-8f)), pp1 = splat2(fmaf(e1, inv, 1e-8f));
        u64 pp2 = splat2(fmaf(e2, inv, 1e-8f)), pp3 = splat2(fmaf(e3, inv, 1e-8f));
        u64 pp4 = splat2(fmaf(e4, inv, 1e-8f)), pp5 = splat2(fmaf(e5, inv, 1e-8f));
        u64 pp6 = splat2(fmaf(e6, inv, 1e-8f)), pp7 = splat2(fmaf(e7, inv, 1e-8f));
        ulonglong2* Pq = (ulonglong2*)Pr;
        Pq[0] = make_ulonglong2(pp0, pp1);
        Pq[1] = make_ulonglong2(pp2, pp3);
        Pq[2] = make_ulonglong2(pp4, pp5);
        Pq[3] = make_ulonglong2(pp6, pp7);
    }
    __syncwarp();                          // P visible to all lanes

    // ================= PV: p uniform, V distinct (lane = dim pair) =================
    u64 pv[8];
#pragma unroll
    for (int m = 0; m < 8; ++m) pv[m] = 0ull;

    const float* Pbase = &smem[OFF_W(warp) + W_P];
    const float* Vb0   = &smem[OFF_W(warp) + W_KH0];
    const float* Vb1   = &smem[OFF_W(warp) + W_KH1];

    cp_wait<1>();  __syncwarp();          // Vh0 landed
#pragma unroll
    for (int k = 0; k < 16; ++k) {
        const ulonglong2* Pq = (const ulonglong2*)(Pbase + k * PROW);
        ulonglong2 p01 = Pq[0], p23 = Pq[1], p45 = Pq[2], p67 = Pq[3];
        u64 v = *(const u64*)(Vb0 + k * DIM + (lane << 1));
        fma2(pv[0], p01.x, v); fma2(pv[1], p01.y, v);
        fma2(pv[2], p23.x, v); fma2(pv[3], p23.y, v);
        fma2(pv[4], p45.x, v); fma2(pv[5], p45.y, v);
        fma2(pv[6], p67.x, v); fma2(pv[7], p67.y, v);
    }
    cp_wait<0>();  __syncwarp();          // Vh1 landed
#pragma unroll
    for (int k = 0; k < 16; ++k) {
        const ulonglong2* Pq = (const ulonglong2*)(Pbase + (k + 16) * PROW);
        ulonglong2 p01 = Pq[0], p23 = Pq[1], p45 = Pq[2], p67 = Pq[3];
        u64 v = *(const u64*)(Vb1 + k * DIM + (lane << 1));
        fma2(pv[0], p01.x, v); fma2(pv[1], p01.y, v);
        fma2(pv[2], p23.x, v); fma2(pv[3], p23.y, v);
        fma2(pv[4], p45.x, v); fma2(pv[5], p45.y, v);
        fma2(pv[6], p67.x, v); fma2(pv[7], p67.y, v);
    }
    __syncwarp();

    // ================= per-warp epilogue =================
    // pv: lane owns out[m][2*lane .. 2*lane+1] -> red area (reuses KH0 region)
    {
        float* red = &smem[OFF_W(warp)];
#pragma unroll
        for (int m = 0; m < 8; ++m)
            *(u64*)&red[m * 64 + (lane << 1)] = pv[m];
        // colsum: sum splatted p (lo half) over the 32 keys, from P
        if (lane < 8) {
            float s = 0.f;
#pragma unroll
            for (int k = 0; k < 32; ++k)
                s += Pbase[k * PROW + (lane << 1)];
            red[512 + lane] = s;
        }
    }
    __syncthreads();

    const int pidx = (b * CPB + chunk) * NQ;
    if (tid < 8) {
        float s = 0.f;
#pragma unroll
        for (int w = 0; w < 4; ++w) s += smem[OFF_W(w) + 512 + tid];
        g_cs[pidx + tid] = s;
    }
    {
        int off = tid * 4;                    // 128 threads x float4 = 512 floats
        float4 s = make_float4(0.f, 0.f, 0.f, 0.f);
#pragma unroll
        for (int w = 0; w < 4; ++w) {
            float4 p = *(const float4*)&smem[OFF_W(w) + off];
            s.x += p.x; s.y += p.y; s.z += p.z; s.w += p.w;
        }
        *(float4*)&g_pv[(size_t)pidx * DIM + off] = s;
    }

    // ---- fused finalize: last chunk CTA of this batch ----
    __syncthreads();
    if (tid == 0) {
        __threadfence();
        unsigned old = atomicAdd(&g_cnt[b], 1u);
        s_last = (old == CPB - 1) ? 1 : 0;
    }
    __syncthreads();
    if (s_last) {
        __threadfence();
        int qm = tid >> 4, v4 = (tid & 15) << 2;
        float c0 = 0.f;
        float4 acc4 = make_float4(0.f, 0.f, 0.f, 0.f);
#pragma unroll
        for (int c = 0; c < CPB; ++c) {
            c0 += g_cs[(b * CPB + c) * NQ + qm];
            float4 p = *(const float4*)&g_pv[((size_t)(b * CPB + c) * NQ + qm) * DIM + v4];
            acc4.x += p.x; acc4.y += p.y; acc4.z += p.z; acc4.w += p.w;
        }
        float inv = 1.0f / c0;
        *(float4*)&out[((size_t)b * NQ + qm) * DIM + v4] =
            make_float4(acc4.x * inv, acc4.y * inv, acc4.z * inv, acc4.w * inv);
        if (tid == 0) g_cnt[b] = 0;   // reset for next graph replay
    }
}

extern "C" void kernel_launch(void* const* d_in, const int* in_sizes, int n_in,
                              void* d_out, int out_size) {
    const float* keys  = (const float*)d_in[0];
    const float* vals  = (const float*)d_in[1];
    const float* query = (const float*)d_in[2];
    float* out = (float*)d_out;

    cudaFuncSetAttribute(attn_fused,
                         cudaFuncAttributeMaxDynamicSharedMemorySize,
                         SMEM_FLOATS * sizeof(float));
    attn_fused<<<BQ * CPB, 128, SMEM_FLOATS * sizeof(float)>>>(keys, vals, query, out);
}